// round 7
// baseline (speedup 1.0000x reference)
#include <cuda_runtime.h>

#define HH 512
#define WW 512
#define BB 32
#define HW (HH * WW)
#define NSTRIPS 10          // 56 output cols per strip, 10*56=560 >= 512
#define OUTW 56
#define HS 32               // rows per y-chunk
#define NYC (HH / HS)       // 16
#define NTASKS (BB * NYC * NSTRIPS)   // 5120 warp-tasks
#define WPB 8               // warps per block
#define NBLOCKS (NTASKS / WPB)        // 640

__device__ float g_partials[NBLOCKS];
__device__ unsigned g_count = 0;

// 5-tap gaussian (sigma=1), fp32-normalized (validated R4/R5: rel_err 9.8e-8)
#define W0 0.054488685f
#define W1 0.244201342f
#define W2 0.402619947f

// hblur pair (cols c0, c0+1) of gray((x+1)/2) at global row yy, one image.
// Lanes own consecutive col pairs; gaussian halo via 4 shuffles. Zero outside.
__device__ __forceinline__ float2 hblur_row(const float* __restrict__ base,
                                            int yy, int c0, bool colok) {
    float ge = 0.0f, go = 0.0f;
    if (colok && (unsigned)yy < (unsigned)HH) {
        int idx = yy * WW + c0;                       // c0 even -> 8B aligned
        float2 r = *(const float2*)(base + idx);
        float2 g = *(const float2*)(base + HW + idx);
        float2 b = *(const float2*)(base + 2 * HW + idx);
        ge = fmaf(0.5f, fmaf(0.299f, r.x, fmaf(0.587f, g.x, 0.114f * b.x)), 0.5f);
        go = fmaf(0.5f, fmaf(0.299f, r.y, fmaf(0.587f, g.y, 0.114f * b.y)), 0.5f);
    }
    const unsigned m = 0xffffffffu;
    float pge = __shfl_up_sync(m, ge, 1);    // gray(c0-2)
    float pgo = __shfl_up_sync(m, go, 1);    // gray(c0-1)
    float nge = __shfl_down_sync(m, ge, 1);  // gray(c0+2)
    float ngo = __shfl_down_sync(m, go, 1);  // gray(c0+3)
    float2 h;
    h.x = fmaf(W0, pge + nge, fmaf(W1, pgo + go, W2 * ge));   // hblur(c0)
    h.y = fmaf(W0, pgo + ngo, fmaf(W1, ge + nge, W2 * go));   // hblur(c0+1)
    return h;
}

__device__ __forceinline__ float2 vblur5(const float2 h[5]) {
    float2 v;
    v.x = fmaf(W0, h[0].x + h[4].x, fmaf(W1, h[1].x + h[3].x, W2 * h[2].x));
    v.y = fmaf(W0, h[0].y + h[4].y, fmaf(W1, h[1].y + h[3].y, W2 * h[2].y));
    return v;
}

__global__ __launch_bounds__(256)
void edge_loss_fused(const float* __restrict__ gen, const float* __restrict__ real_,
                     float* __restrict__ out, int out_size) {
    __shared__ float wsum[WPB];
    __shared__ bool amLast;

    const int tid  = threadIdx.x;
    const int lane = tid & 31;
    const int wid  = tid >> 5;
    const int task = blockIdx.x * WPB + wid;      // 0..5119
    const int s    = task % NSTRIPS;
    const int tb   = task / NSTRIPS;
    const int yc   = tb % NYC;
    const int b    = tb / NYC;                    // 0..31

    const int  c0     = OUTW * s - 4 + 2 * lane;  // even; lane pair = (c0, c0+1)
    const bool colok  = (unsigned)c0 < (unsigned)WW;
    const int  ybase  = yc * HS;
    const bool outlane = (lane >= 2) && (lane <= 29) && colok;
    const unsigned m = 0xffffffffu;

    const float* A  = gen   + (size_t)b * 3 * HW;
    const float* Bq = real_ + (size_t)b * 3 * HW;

    // --- prologue: hblur window rows [ybase-3 .. ybase+1] for both images ---
    float2 h0[5], h1[5];
    #pragma unroll
    for (int k = 0; k < 5; ++k) {
        h0[k] = hblur_row(A,  ybase - 3 + k, c0, colok);
        h1[k] = hblur_row(Bq, ybase - 3 + k, c0, colok);
    }

    // va = vblur(ybase-1): masked 0 outside image (laplacian zero-pads the BLUR)
    float2 va0 = vblur5(h0), va1 = vblur5(h1);
    if (!(colok && (unsigned)(ybase - 1) < (unsigned)HH)) {
        va0.x = va0.y = va1.x = va1.y = 0.0f;
    }

    // advance window to rows [ybase-2 .. ybase+2]; vb = vblur(ybase)
    #pragma unroll
    for (int k = 0; k < 4; ++k) { h0[k] = h0[k + 1]; h1[k] = h1[k + 1]; }
    h0[4] = hblur_row(A,  ybase + 2, c0, colok);
    h1[4] = hblur_row(Bq, ybase + 2, c0, colok);
    float2 vb0 = vblur5(h0), vb1 = vblur5(h1);
    if (!colok) { vb0.x = vb0.y = vb1.x = vb1.y = 0.0f; }   // ybase always in image

    float acc = 0.0f;

    for (int t = 0; t < HS; ++t) {
        // load hblur row ybase+3+t; vc = vblur(ybase+1+t), masked
        #pragma unroll
        for (int k = 0; k < 4; ++k) { h0[k] = h0[k + 1]; h1[k] = h1[k + 1]; }
        h0[4] = hblur_row(A,  ybase + 3 + t, c0, colok);
        h1[4] = hblur_row(Bq, ybase + 3 + t, c0, colok);
        float2 vc0 = vblur5(h0), vc1 = vblur5(h1);
        if (!(colok && (unsigned)(ybase + 1 + t) < (unsigned)HH)) {
            vc0.x = vc0.y = vc1.x = vc1.y = 0.0f;
        }

        // laplacian at output row ybase+t (vertical: va/vc; horizontal: pair + shuffles)
        float pv0 = __shfl_up_sync(m, vb0.y, 1);    // vblur(y, c0-1)
        float nv0 = __shfl_down_sync(m, vb0.x, 1);  // vblur(y, c0+2)
        float pv1 = __shfl_up_sync(m, vb1.y, 1);
        float nv1 = __shfl_down_sync(m, vb1.x, 1);

        float l0e = va0.x + vc0.x + pv0   + vb0.y - 4.0f * vb0.x;
        float l0o = va0.y + vc0.y + vb0.x + nv0   - 4.0f * vb0.y;
        float l1e = va1.x + vc1.x + pv1   + vb1.y - 4.0f * vb1.x;
        float l1o = va1.y + vc1.y + vb1.x + nv1   - 4.0f * vb1.y;

        if (outlane) {
            acc += fabsf(fabsf(l0e) - fabsf(l1e)) + fabsf(fabsf(l0o) - fabsf(l1o));
        }

        va0 = vb0; va1 = vb1;
        vb0 = vc0; vb1 = vc1;
    }

    // --- deterministic block reduction ---
    #pragma unroll
    for (int o = 16; o; o >>= 1) acc += __shfl_xor_sync(m, acc, o);
    if (lane == 0) wsum[wid] = acc;
    __syncthreads();
    if (tid == 0) {
        float t = 0.0f;
        #pragma unroll
        for (int k = 0; k < WPB; ++k) t += wsum[k];
        g_partials[blockIdx.x] = t;
        __threadfence();
        unsigned v = atomicAdd(&g_count, 1u);
        amLast = (v == (unsigned)(NBLOCKS - 1));
    }
    __syncthreads();

    // --- last block finalizes: fixed-order partial sum (deterministic) ---
    if (amLast) {
        __threadfence();
        float s2 = 0.0f;
        #pragma unroll
        for (int k = 0; k * 256 < NBLOCKS; ++k) {
            int idx = tid + k * 256;
            if (idx < NBLOCKS) s2 += g_partials[idx];
        }
        #pragma unroll
        for (int o = 16; o; o >>= 1) s2 += __shfl_xor_sync(m, s2, o);
        __syncthreads();            // wsum reuse
        if (lane == 0) wsum[wid] = s2;
        __syncthreads();
        if (tid == 0) {
            float t = 0.0f;
            #pragma unroll
            for (int k = 0; k < WPB; ++k) t += wsum[k];
            out[0] = t * (1.0f / 8388608.0f);   // mean over B*1*H*W
            g_count = 0;                        // reset for next graph replay
        }
        for (int l = 1 + tid; l < out_size; l += 256) out[l] = 0.0f;
    }
}

extern "C" void kernel_launch(void* const* d_in, const int* in_sizes, int n_in,
                              void* d_out, int out_size) {
    const float* gen   = (const float*)d_in[0];
    const float* real_ = (const float*)d_in[1];
    edge_loss_fused<<<NBLOCKS, 256>>>(gen, real_, (float*)d_out, out_size);
}

// round 8
// speedup vs baseline: 1.0190x; 1.0190x over previous
#include <cuda_runtime.h>

#define HH 512
#define WW 512
#define BB 32
#define HW (HH * WW)
#define NSTRIPS 10          // 56 output cols per strip, 10*56=560 >= 512
#define OUTW 56
#define HS 64               // rows per y-chunk  (R5-validated optimum)
#define NYC (HH / HS)       // 8
#define NTASKS (BB * NYC * NSTRIPS)   // 2560 warp-tasks
#define WPB 8               // warps per block
#define NBLOCKS (NTASKS / WPB)        // 320

__device__ float g_partials[NBLOCKS];
__device__ unsigned g_count = 0;

// 5-tap gaussian (sigma=1), fp32-normalized (validated: rel_err 9.8e-8)
#define W0 0.054488685f
#define W1 0.244201342f
#define W2 0.402619947f

// hblur pair (cols c0, c0+1) of gray((x+1)/2) at global row yy, one image.
// Lanes own consecutive col pairs; gaussian halo via 4 shuffles. Zero outside.
__device__ __forceinline__ float2 hblur_row(const float* __restrict__ base,
                                            int yy, int c0, bool colok) {
    float ge = 0.0f, go = 0.0f;
    if (colok && (unsigned)yy < (unsigned)HH) {
        int idx = yy * WW + c0;                       // c0 even -> 8B aligned
        float2 r = *(const float2*)(base + idx);
        float2 g = *(const float2*)(base + HW + idx);
        float2 b = *(const float2*)(base + 2 * HW + idx);
        ge = fmaf(0.5f, fmaf(0.299f, r.x, fmaf(0.587f, g.x, 0.114f * b.x)), 0.5f);
        go = fmaf(0.5f, fmaf(0.299f, r.y, fmaf(0.587f, g.y, 0.114f * b.y)), 0.5f);
    }
    const unsigned m = 0xffffffffu;
    float pge = __shfl_up_sync(m, ge, 1);    // gray(c0-2)
    float pgo = __shfl_up_sync(m, go, 1);    // gray(c0-1)
    float nge = __shfl_down_sync(m, ge, 1);  // gray(c0+2)
    float ngo = __shfl_down_sync(m, go, 1);  // gray(c0+3)
    float2 h;
    h.x = fmaf(W0, pge + nge, fmaf(W1, pgo + go, W2 * ge));   // hblur(c0)
    h.y = fmaf(W0, pgo + ngo, fmaf(W1, ge + nge, W2 * go));   // hblur(c0+1)
    return h;
}

__device__ __forceinline__ float2 vblur5(const float2 h[5]) {
    float2 v;
    v.x = fmaf(W0, h[0].x + h[4].x, fmaf(W1, h[1].x + h[3].x, W2 * h[2].x));
    v.y = fmaf(W0, h[0].y + h[4].y, fmaf(W1, h[1].y + h[3].y, W2 * h[2].y));
    return v;
}

__global__ __launch_bounds__(256)
void edge_loss_fused(const float* __restrict__ gen, const float* __restrict__ real_,
                     float* __restrict__ out, int out_size) {
    __shared__ float wsum[WPB];
    __shared__ bool amLast;

    const int tid  = threadIdx.x;
    const int lane = tid & 31;
    const int wid  = tid >> 5;
    const int task = blockIdx.x * WPB + wid;      // 0..2559
    const int s    = task % NSTRIPS;
    const int tb   = task / NSTRIPS;
    const int yc   = tb % NYC;
    const int b    = tb / NYC;                    // 0..31

    const int  c0     = OUTW * s - 4 + 2 * lane;  // even; lane pair = (c0, c0+1)
    const bool colok  = (unsigned)c0 < (unsigned)WW;
    const int  ybase  = yc * HS;
    const bool outlane = (lane >= 2) && (lane <= 29) && colok;
    const unsigned m = 0xffffffffu;

    const float* A  = gen   + (size_t)b * 3 * HW;
    const float* Bq = real_ + (size_t)b * 3 * HW;

    // --- prologue: hblur window rows [ybase-3 .. ybase+1] for both images ---
    float2 h0[5], h1[5];
    #pragma unroll
    for (int k = 0; k < 5; ++k) {
        h0[k] = hblur_row(A,  ybase - 3 + k, c0, colok);
        h1[k] = hblur_row(Bq, ybase - 3 + k, c0, colok);
    }

    // va = vblur(ybase-1): masked 0 outside image (laplacian zero-pads the BLUR)
    float2 va0 = vblur5(h0), va1 = vblur5(h1);
    if (!(colok && (unsigned)(ybase - 1) < (unsigned)HH)) {
        va0.x = va0.y = va1.x = va1.y = 0.0f;
    }

    // advance window to rows [ybase-2 .. ybase+2]; vb = vblur(ybase)
    #pragma unroll
    for (int k = 0; k < 4; ++k) { h0[k] = h0[k + 1]; h1[k] = h1[k + 1]; }
    h0[4] = hblur_row(A,  ybase + 2, c0, colok);
    h1[4] = hblur_row(Bq, ybase + 2, c0, colok);
    float2 vb0 = vblur5(h0), vb1 = vblur5(h1);
    if (!colok) { vb0.x = vb0.y = vb1.x = vb1.y = 0.0f; }   // ybase always in image

    float acc = 0.0f;

    for (int t = 0; t < HS; ++t) {
        // load hblur row ybase+3+t; vc = vblur(ybase+1+t), masked
        #pragma unroll
        for (int k = 0; k < 4; ++k) { h0[k] = h0[k + 1]; h1[k] = h1[k + 1]; }
        h0[4] = hblur_row(A,  ybase + 3 + t, c0, colok);
        h1[4] = hblur_row(Bq, ybase + 3 + t, c0, colok);
        float2 vc0 = vblur5(h0), vc1 = vblur5(h1);
        if (!(colok && (unsigned)(ybase + 1 + t) < (unsigned)HH)) {
            vc0.x = vc0.y = vc1.x = vc1.y = 0.0f;
        }

        // laplacian at output row ybase+t (vertical: va/vc; horizontal: pair + shuffles)
        float pv0 = __shfl_up_sync(m, vb0.y, 1);    // vblur(y, c0-1)
        float nv0 = __shfl_down_sync(m, vb0.x, 1);  // vblur(y, c0+2)
        float pv1 = __shfl_up_sync(m, vb1.y, 1);
        float nv1 = __shfl_down_sync(m, vb1.x, 1);

        float l0e = va0.x + vc0.x + pv0   + vb0.y - 4.0f * vb0.x;
        float l0o = va0.y + vc0.y + vb0.x + nv0   - 4.0f * vb0.y;
        float l1e = va1.x + vc1.x + pv1   + vb1.y - 4.0f * vb1.x;
        float l1o = va1.y + vc1.y + vb1.x + nv1   - 4.0f * vb1.y;

        if (outlane) {
            acc += fabsf(fabsf(l0e) - fabsf(l1e)) + fabsf(fabsf(l0o) - fabsf(l1o));
        }

        va0 = vb0; va1 = vb1;
        vb0 = vc0; vb1 = vc1;
    }

    // --- deterministic block reduction ---
    #pragma unroll
    for (int o = 16; o; o >>= 1) acc += __shfl_xor_sync(m, acc, o);
    if (lane == 0) wsum[wid] = acc;
    __syncthreads();
    if (tid == 0) {
        float t = 0.0f;
        #pragma unroll
        for (int k = 0; k < WPB; ++k) t += wsum[k];
        g_partials[blockIdx.x] = t;
        __threadfence();
        unsigned v = atomicAdd(&g_count, 1u);
        amLast = (v == (unsigned)(NBLOCKS - 1));
    }
    __syncthreads();

    // --- last block finalizes: fixed-order partial sum (deterministic) ---
    if (amLast) {
        __threadfence();
        float s2 = 0.0f;
        #pragma unroll
        for (int k = 0; k * 256 < NBLOCKS; ++k) {
            int idx = tid + k * 256;
            if (idx < NBLOCKS) s2 += g_partials[idx];
        }
        #pragma unroll
        for (int o = 16; o; o >>= 1) s2 += __shfl_xor_sync(m, s2, o);
        __syncthreads();            // wsum reuse
        if (lane == 0) wsum[wid] = s2;
        __syncthreads();
        if (tid == 0) {
            float t = 0.0f;
            #pragma unroll
            for (int k = 0; k < WPB; ++k) t += wsum[k];
            out[0] = t * (1.0f / 8388608.0f);   // mean over B*1*H*W
            g_count = 0;                        // reset for next graph replay
        }
        for (int l = 1 + tid; l < out_size; l += 256) out[l] = 0.0f;
    }
}

extern "C" void kernel_launch(void* const* d_in, const int* in_sizes, int n_in,
                              void* d_out, int out_size) {
    const float* gen   = (const float*)d_in[0];
    const float* real_ = (const float*)d_in[1];
    edge_loss_fused<<<NBLOCKS, 256>>>(gen, real_, (float*)d_out, out_size);
}

// round 9
// speedup vs baseline: 1.4368x; 1.4100x over previous
#include <cuda_runtime.h>

#define HH 512
#define WW 512
#define BB 32
#define HW (HH * WW)
#define NSTRIPS 10          // 56 output cols per strip, 10*56=560 >= 512
#define OUTW 56
#define HS 64               // rows per y-chunk
#define NYC (HH / HS)       // 8
#define NTASKS (BB * NYC * NSTRIPS)   // 2560 warp-tasks
#define NBLOCKS (NTASKS / 8)          // 320 blocks of 8 warps

__device__ float g_partials[NBLOCKS];

// 5-tap gaussian (sigma=1), fp32-normalized (validated R4: rel_err 9.8e-8)
#define W0 0.054488685f
#define W1 0.244201342f
#define W2 0.402619947f

// Compute horizontal-gaussian pair (cols c0, c0+1) of gray((x+1)/2) at global
// row yy for one image. Gray outside the image (row or cols) is 0 (conv zero-pad).
// Neighbor gray columns come from lane shuffles (lanes own consecutive col pairs).
__device__ __forceinline__ float2 hblur_row(const float* __restrict__ base,
                                            int yy, int c0, bool colok) {
    float ge = 0.0f, go = 0.0f;
    if (colok && (unsigned)yy < (unsigned)HH) {
        int idx = yy * WW + c0;                       // c0 even -> 8B aligned
        float2 r = *(const float2*)(base + idx);
        float2 g = *(const float2*)(base + HW + idx);
        float2 b = *(const float2*)(base + 2 * HW + idx);
        ge = fmaf(0.5f, fmaf(0.299f, r.x, fmaf(0.587f, g.x, 0.114f * b.x)), 0.5f);
        go = fmaf(0.5f, fmaf(0.299f, r.y, fmaf(0.587f, g.y, 0.114f * b.y)), 0.5f);
    }
    const unsigned m = 0xffffffffu;
    float pge = __shfl_up_sync(m, ge, 1);    // gray(c0-2)
    float pgo = __shfl_up_sync(m, go, 1);    // gray(c0-1)
    float nge = __shfl_down_sync(m, ge, 1);  // gray(c0+2)
    float ngo = __shfl_down_sync(m, go, 1);  // gray(c0+3)
    float2 h;
    h.x = fmaf(W0, pge + nge, fmaf(W1, pgo + go, W2 * ge));   // hblur(c0)
    h.y = fmaf(W0, pgo + ngo, fmaf(W1, ge + nge, W2 * go));   // hblur(c0+1)
    return h;
}

// Vertical 5-tap over the rolling hblur window (rows r-2..r+2 in h[0..4])
__device__ __forceinline__ float2 vblur5(const float2 h[5]) {
    float2 v;
    v.x = fmaf(W0, h[0].x + h[4].x, fmaf(W1, h[1].x + h[3].x, W2 * h[2].x));
    v.y = fmaf(W0, h[0].y + h[4].y, fmaf(W1, h[1].y + h[3].y, W2 * h[2].y));
    return v;
}

__global__ __launch_bounds__(256)
void edge_loss_fused(const float* __restrict__ gen, const float* __restrict__ real_) {
    __shared__ float wsum[8];

    const int tid  = threadIdx.x;
    const int lane = tid & 31;
    const int wid  = tid >> 5;
    const int task = blockIdx.x * 8 + wid;        // 0..2559
    const int s    = task % NSTRIPS;
    const int tb   = task / NSTRIPS;
    const int yc   = tb % NYC;
    const int b    = tb / NYC;                    // 0..31

    const int  c0     = OUTW * s - 4 + 2 * lane;  // even; lane pair = (c0, c0+1)
    const bool colok  = (unsigned)c0 < (unsigned)WW;
    const int  ybase  = yc * HS;
    const bool outlane = (lane >= 2) && (lane <= 29) && colok;
    const unsigned m = 0xffffffffu;

    const float* A  = gen   + (size_t)b * 3 * HW;
    const float* Bq = real_ + (size_t)b * 3 * HW;

    // --- prologue: hblur window rows [ybase-3 .. ybase+1] for both images ---
    float2 h0[5], h1[5];
    #pragma unroll
    for (int k = 0; k < 5; ++k) {
        h0[k] = hblur_row(A,  ybase - 3 + k, c0, colok);
        h1[k] = hblur_row(Bq, ybase - 3 + k, c0, colok);
    }

    // va = vblur(ybase-1): masked 0 outside image (lap zero-pads the BLUR)
    float2 va0 = vblur5(h0), va1 = vblur5(h1);
    if (!(colok && (unsigned)(ybase - 1) < (unsigned)HH)) {
        va0.x = va0.y = va1.x = va1.y = 0.0f;
    }

    // advance window to rows [ybase-2 .. ybase+2]; vb = vblur(ybase)
    #pragma unroll
    for (int k = 0; k < 4; ++k) { h0[k] = h0[k + 1]; h1[k] = h1[k + 1]; }
    h0[4] = hblur_row(A,  ybase + 2, c0, colok);
    h1[4] = hblur_row(Bq, ybase + 2, c0, colok);
    float2 vb0 = vblur5(h0), vb1 = vblur5(h1);
    if (!colok) { vb0.x = vb0.y = vb1.x = vb1.y = 0.0f; }   // ybase always in image

    float acc = 0.0f;

    for (int t = 0; t < HS; ++t) {
        // load hblur row ybase+3+t; vc = vblur(ybase+1+t)
        #pragma unroll
        for (int k = 0; k < 4; ++k) { h0[k] = h0[k + 1]; h1[k] = h1[k + 1]; }
        h0[4] = hblur_row(A,  ybase + 3 + t, c0, colok);
        h1[4] = hblur_row(Bq, ybase + 3 + t, c0, colok);
        float2 vc0 = vblur5(h0), vc1 = vblur5(h1);
        if (!(colok && (unsigned)(ybase + 1 + t) < (unsigned)HH)) {
            vc0.x = vc0.y = vc1.x = vc1.y = 0.0f;
        }

        // laplacian at output row y = ybase + t (cross: va/vc vertical, shuffles horizontal)
        float pv0 = __shfl_up_sync(m, vb0.y, 1);    // v(y, c0-1) img0
        float nv0 = __shfl_down_sync(m, vb0.x, 1);  // v(y, c0+2) img0
        float pv1 = __shfl_up_sync(m, vb1.y, 1);
        float nv1 = __shfl_down_sync(m, vb1.x, 1);

        float l0e = va0.x + vc0.x + pv0   + vb0.y - 4.0f * vb0.x;
        float l0o = va0.y + vc0.y + vb0.x + nv0   - 4.0f * vb0.y;
        float l1e = va1.x + vc1.x + pv1   + vb1.y - 4.0f * vb1.x;
        float l1o = va1.y + vc1.y + vb1.x + nv1   - 4.0f * vb1.y;

        if (outlane) {
            acc += fabsf(fabsf(l0e) - fabsf(l1e)) + fabsf(fabsf(l0o) - fabsf(l1o));
        }

        va0 = vb0; va1 = vb1;
        vb0 = vc0; vb1 = vc1;
    }

    // --- deterministic block reduction ---
    #pragma unroll
    for (int o = 16; o; o >>= 1) acc += __shfl_xor_sync(m, acc, o);
    if (lane == 0) wsum[wid] = acc;
    __syncthreads();
    if (tid == 0) {
        float t = 0.0f;
        #pragma unroll
        for (int k = 0; k < 8; ++k) t += wsum[k];
        g_partials[blockIdx.x] = t;
    }
}

__global__ __launch_bounds__(256)
void finalize_kernel(float* __restrict__ out, int out_size) {
    __shared__ float wsum[8];
    const int tid = threadIdx.x;
    float s = 0.0f;
    for (int l = tid; l < NBLOCKS; l += 256) s += g_partials[l];
    #pragma unroll
    for (int o = 16; o; o >>= 1) s += __shfl_xor_sync(0xffffffffu, s, o);
    if ((tid & 31) == 0) wsum[tid >> 5] = s;
    __syncthreads();
    if (tid == 0) {
        float t = 0.0f;
        #pragma unroll
        for (int k = 0; k < 8; ++k) t += wsum[k];
        out[0] = t * (1.0f / 8388608.0f);   // mean over B*1*H*W
    }
    for (int l = 1 + tid; l < out_size; l += 256) out[l] = 0.0f;
}

extern "C" void kernel_launch(void* const* d_in, const int* in_sizes, int n_in,
                              void* d_out, int out_size) {
    const float* gen   = (const float*)d_in[0];
    const float* real_ = (const float*)d_in[1];
    edge_loss_fused<<<NBLOCKS, 256>>>(gen, real_);
    finalize_kernel<<<1, 256>>>((float*)d_out, out_size);
}